// round 10
// baseline (speedup 1.0000x reference)
#include <cuda_runtime.h>

#define NN 100000
#define EMAX 1600000
#define FF 128
#define HH 64

// ---- persistent scratch (no allocations allowed) ----
__device__ float g_AGG[NN * FF];       // aggregation output (128-wide L1, 64-wide L2/L3)
__device__ float g_MID[NN * HH];       // after first linear + relu (layer 1 only)
__device__ float g_H2 [NN * HH];       // after second linear (pre-BN)
__device__ float g_H  [NN * HH];       // node features (post BN/relu/residual)
__device__ float g_stats[2 * HH];      // sum, sumsq per channel
__device__ float g_bn   [2 * HH];      // scale, shift per channel
__device__ int   g_is64;               // edge_index dtype flag (runtime-detected)
// CSC structure (built once per call, reused by all 3 layers)
__device__ int  g_rowptr[NN + 1];      // exclusive prefix of in-degrees
__device__ int  g_cursor[NN];          // counts during hist, then scatter cursors
__device__ int  g_blocksum[128];       // scan partials
__device__ int2 g_edges[EMAX];         // per-dst-grouped {src, bitcast(weight)}

// ===========================================================================
// build init: zero cursors; block 0 also detects edge_index dtype.
// int64 indices < 2^31 => all odd 32-bit words are zero. With int32 data the
// odd words are random node ids -> nonzero w.h.p.
// ===========================================================================
__global__ void build_init_kernel(const int* __restrict__ w) {
    if (blockIdx.x == 0 && threadIdx.x == 0) {
        int any = 0;
        #pragma unroll
        for (int i = 1; i < 128; i += 2) any |= w[i];
        g_is64 = (any == 0) ? 1 : 0;
    }
    int i = blockIdx.x * blockDim.x + threadIdx.x;
    if (i < NN) g_cursor[i] = 0;
}

__device__ __forceinline__ int load_src(const int* w, int E, int e, int is64) {
    return is64 ? __ldg(w + 2 * e) : __ldg(w + e);
}
__device__ __forceinline__ int load_dst(const int* w, int E, int e, int is64) {
    return is64 ? __ldg(w + 2 * (E + e)) : __ldg(w + E + e);
}

// ===========================================================================
// CSC build: hist -> scan1 -> scan2 -> scanAdd -> scatter
// ===========================================================================
__global__ void hist_kernel(const int* __restrict__ ei, int E) {
    int e = blockIdx.x * blockDim.x + threadIdx.x;
    if (e >= E) return;
    int is64 = g_is64;
    atomicAdd(&g_cursor[load_dst(ei, E, e, is64)], 1);
}

__global__ void scan1_kernel(int n) {
    __shared__ int tmp[1024];
    int i = blockIdx.x * 1024 + threadIdx.x;
    int v = (i < n) ? g_cursor[i] : 0;
    tmp[threadIdx.x] = v;
    __syncthreads();
    for (int off = 1; off < 1024; off <<= 1) {
        int t = (threadIdx.x >= off) ? tmp[threadIdx.x - off] : 0;
        __syncthreads();
        tmp[threadIdx.x] += t;
        __syncthreads();
    }
    if (i < n) g_rowptr[i] = tmp[threadIdx.x] - v;   // exclusive, block-local
    if (threadIdx.x == 1023) g_blocksum[blockIdx.x] = tmp[1023];
}

__global__ void scan2_kernel(int nb) {
    __shared__ int tmp[128];
    int v = (threadIdx.x < nb) ? g_blocksum[threadIdx.x] : 0;
    tmp[threadIdx.x] = v;
    __syncthreads();
    for (int off = 1; off < 128; off <<= 1) {
        int t = (threadIdx.x >= off) ? tmp[threadIdx.x - off] : 0;
        __syncthreads();
        tmp[threadIdx.x] += t;
        __syncthreads();
    }
    if (threadIdx.x < nb) g_blocksum[threadIdx.x] = tmp[threadIdx.x] - v;
}

__global__ void scanadd_kernel(int E) {
    int i = blockIdx.x * blockDim.x + threadIdx.x;
    if (i < NN) {
        int r = g_rowptr[i] + g_blocksum[i >> 10];
        g_rowptr[i] = r;
        g_cursor[i] = r;                  // scatter cursor
    }
    if (i == 0) g_rowptr[NN] = E;
}

__global__ void scatter_kernel(const int* __restrict__ ei,
                               const float* __restrict__ ew, int E) {
    int e = blockIdx.x * blockDim.x + threadIdx.x;
    if (e >= E) return;
    int is64 = g_is64;
    int s = load_src(ei, E, e, is64);
    int d = load_dst(ei, E, e, is64);
    float w = __ldg(ew + e);
    int pos = atomicAdd(&g_cursor[d], 1);
    g_edges[pos] = make_int2(s, __float_as_int(w));
}

// ===========================================================================
// Pull aggregation, F=128: warp per node, float4 per lane, acc in registers.
//   g_AGG[node] = (1+eps)*x[node] + sum_edges w * x[src]
// Edge loop unrolled x4: 4 independent gathers in flight.
// Block 0 also zeroes the batch-stat accumulators for this layer.
// ===========================================================================
__global__ void pull128_kernel(const float* __restrict__ x,
                               const float* __restrict__ eps) {
    if (blockIdx.x == 0 && threadIdx.x < 128) g_stats[threadIdx.x] = 0.0f;
    int node = blockIdx.x * (blockDim.x >> 5) + (threadIdx.x >> 5);
    if (node >= NN) return;
    int l = threadIdx.x & 31;
    int beg = __ldg(g_rowptr + node);
    int end = __ldg(g_rowptr + node + 1);
    float s = 1.0f + __ldg(eps);
    float4 acc = __ldg(((const float4*)x) + (size_t)node * 32 + l);
    acc.x *= s; acc.y *= s; acc.z *= s; acc.w *= s;
    int p = beg;
    for (; p + 4 <= end; p += 4) {
        int2 e0 = __ldg(g_edges + p);
        int2 e1 = __ldg(g_edges + p + 1);
        int2 e2 = __ldg(g_edges + p + 2);
        int2 e3 = __ldg(g_edges + p + 3);
        float4 v0 = __ldg(((const float4*)x) + (size_t)e0.x * 32 + l);
        float4 v1 = __ldg(((const float4*)x) + (size_t)e1.x * 32 + l);
        float4 v2 = __ldg(((const float4*)x) + (size_t)e2.x * 32 + l);
        float4 v3 = __ldg(((const float4*)x) + (size_t)e3.x * 32 + l);
        float w0 = __int_as_float(e0.y), w1 = __int_as_float(e1.y);
        float w2 = __int_as_float(e2.y), w3 = __int_as_float(e3.y);
        acc.x += w0 * v0.x; acc.y += w0 * v0.y; acc.z += w0 * v0.z; acc.w += w0 * v0.w;
        acc.x += w1 * v1.x; acc.y += w1 * v1.y; acc.z += w1 * v1.z; acc.w += w1 * v1.w;
        acc.x += w2 * v2.x; acc.y += w2 * v2.y; acc.z += w2 * v2.z; acc.w += w2 * v2.w;
        acc.x += w3 * v3.x; acc.y += w3 * v3.y; acc.z += w3 * v3.z; acc.w += w3 * v3.w;
    }
    for (; p < end; p++) {
        int2 e0 = __ldg(g_edges + p);
        float w0 = __int_as_float(e0.y);
        float4 v0 = __ldg(((const float4*)x) + (size_t)e0.x * 32 + l);
        acc.x += w0 * v0.x; acc.y += w0 * v0.y;
        acc.z += w0 * v0.z; acc.w += w0 * v0.w;
    }
    ((float4*)g_AGG)[(size_t)node * 32 + l] = acc;
}

// Pull aggregation, F=64 (reads g_H): 16 lanes per node, 2 nodes per warp.
__global__ void pull64_kernel(const float* __restrict__ eps) {
    int node = blockIdx.x * (blockDim.x >> 4) + (threadIdx.x >> 4);
    if (node >= NN) return;
    int l = threadIdx.x & 15;
    int beg = __ldg(g_rowptr + node);
    int end = __ldg(g_rowptr + node + 1);
    float s = 1.0f + __ldg(eps);
    float4 acc = ((const float4*)g_H)[(size_t)node * 16 + l];
    acc.x *= s; acc.y *= s; acc.z *= s; acc.w *= s;
    int p = beg;
    for (; p + 4 <= end; p += 4) {
        int2 e0 = __ldg(g_edges + p);
        int2 e1 = __ldg(g_edges + p + 1);
        int2 e2 = __ldg(g_edges + p + 2);
        int2 e3 = __ldg(g_edges + p + 3);
        float4 v0 = ((const float4*)g_H)[(size_t)e0.x * 16 + l];
        float4 v1 = ((const float4*)g_H)[(size_t)e1.x * 16 + l];
        float4 v2 = ((const float4*)g_H)[(size_t)e2.x * 16 + l];
        float4 v3 = ((const float4*)g_H)[(size_t)e3.x * 16 + l];
        float w0 = __int_as_float(e0.y), w1 = __int_as_float(e1.y);
        float w2 = __int_as_float(e2.y), w3 = __int_as_float(e3.y);
        acc.x += w0 * v0.x; acc.y += w0 * v0.y; acc.z += w0 * v0.z; acc.w += w0 * v0.w;
        acc.x += w1 * v1.x; acc.y += w1 * v1.y; acc.z += w1 * v1.z; acc.w += w1 * v1.w;
        acc.x += w2 * v2.x; acc.y += w2 * v2.y; acc.z += w2 * v2.z; acc.w += w2 * v2.w;
        acc.x += w3 * v3.x; acc.y += w3 * v3.y; acc.z += w3 * v3.z; acc.w += w3 * v3.w;
    }
    for (; p < end; p++) {
        int2 e0 = __ldg(g_edges + p);
        float w0 = __int_as_float(e0.y);
        float4 v0 = ((const float4*)g_H)[(size_t)e0.x * 16 + l];
        acc.x += w0 * v0.x; acc.y += w0 * v0.y;
        acc.z += w0 * v0.z; acc.w += w0 * v0.w;
    }
    ((float4*)g_AGG)[(size_t)node * 16 + l] = acc;
}

// ===========================================================================
// Layer-1 MLP stages (128->64 doesn't fit fused in 48KB static smem).
//   STAGEA=true :  g_MID = relu(g_AGG[.,FIN] @ W + b)
//   STAGEA=false:  g_H2  = g_MID @ W + b  + batch-stat accum
// ===========================================================================
template<int FIN, bool STAGEA>
__global__ void mlp_kernel(const float* __restrict__ W,
                           const float* __restrict__ b) {
    __shared__ float sW[FIN * 64];
    __shared__ float sRow[16 * FIN];
    __shared__ float sB[64];
    const float* in = STAGEA ? g_AGG : g_MID;
    int tid = threadIdx.x;
    for (int i = tid; i < FIN * 16; i += 256)          // FIN*64/4 float4s
        ((float4*)sW)[i] = __ldg(((const float4*)W) + i);
    if (tid < 64) sB[tid] = __ldg(b + tid);
    long long base = (long long)blockIdx.x * (16 * FIN / 4);
    for (int i = tid; i < 16 * FIN / 4; i += 256)
        ((float4*)sRow)[i] = __ldg(((const float4*)in) + base + i);
    __syncthreads();

    int j = tid & 63, grp = tid >> 6;
    const float* r0 = sRow + (grp * 4 + 0) * FIN;
    const float* r1 = sRow + (grp * 4 + 1) * FIN;
    const float* r2 = sRow + (grp * 4 + 2) * FIN;
    const float* r3 = sRow + (grp * 4 + 3) * FIN;
    float a0 = sB[j], a1 = a0, a2 = a0, a3 = a0;
    #pragma unroll 16
    for (int f = 0; f < FIN; f++) {
        float w = sW[f * 64 + j];
        a0 += w * r0[f];
        a1 += w * r1[f];
        a2 += w * r2[f];
        a3 += w * r3[f];
    }
    if (STAGEA) {
        a0 = fmaxf(a0, 0.f); a1 = fmaxf(a1, 0.f);
        a2 = fmaxf(a2, 0.f); a3 = fmaxf(a3, 0.f);
    }
    float* out = STAGEA ? g_MID : g_H2;
    int node0 = blockIdx.x * 16 + grp * 4;
    out[(node0 + 0) * 64 + j] = a0;
    out[(node0 + 1) * 64 + j] = a1;
    out[(node0 + 2) * 64 + j] = a2;
    out[(node0 + 3) * 64 + j] = a3;

    if (!STAGEA) {
        __shared__ float sS[256];
        __shared__ float sQ[256];
        sS[tid] = a0 + a1 + a2 + a3;
        sQ[tid] = a0 * a0 + a1 * a1 + a2 * a2 + a3 * a3;
        __syncthreads();
        if (grp == 0) {
            float S = sS[j] + sS[j + 64] + sS[j + 128] + sS[j + 192];
            float Q = sQ[j] + sQ[j + 64] + sQ[j + 128] + sQ[j + 192];
            atomicAdd(&g_stats[j], S);
            atomicAdd(&g_stats[64 + j], Q);
        }
    }
}

// ===========================================================================
// Fused 64->64->64 MLP (layers 2,3): both GEMMs in one kernel, intermediate
// kept in smem (saves the g_MID round-trip). 42.5KB static smem.
//   g_H2 = (relu(g_AGG @ W1 + b1)) @ W2 + b2   + batch-stat accum
// ===========================================================================
__global__ void mlp2_kernel(const float* __restrict__ W1,
                            const float* __restrict__ b1,
                            const float* __restrict__ W2,
                            const float* __restrict__ b2) {
    __shared__ float sW1[64 * 64];
    __shared__ float sW2[64 * 64];
    __shared__ float sRow[16 * 64];
    __shared__ float sMid[16 * 64];
    __shared__ float sB1[64];
    __shared__ float sB2[64];
    int tid = threadIdx.x;
    for (int i = tid; i < 64 * 16; i += 256) {         // 64*64/4 float4s
        ((float4*)sW1)[i] = __ldg(((const float4*)W1) + i);
        ((float4*)sW2)[i] = __ldg(((const float4*)W2) + i);
    }
    if (tid < 64) { sB1[tid] = __ldg(b1 + tid); sB2[tid] = __ldg(b2 + tid); }
    long long base = (long long)blockIdx.x * (16 * 64 / 4);
    for (int i = tid; i < 16 * 64 / 4; i += 256)
        ((float4*)sRow)[i] = __ldg(((const float4*)g_AGG) + base + i);
    __syncthreads();

    int j = tid & 63, grp = tid >> 6;
    // ---- stage A: sMid = relu(sRow @ W1 + b1) ----
    {
        const float* r0 = sRow + (grp * 4 + 0) * 64;
        const float* r1 = sRow + (grp * 4 + 1) * 64;
        const float* r2 = sRow + (grp * 4 + 2) * 64;
        const float* r3 = sRow + (grp * 4 + 3) * 64;
        float a0 = sB1[j], a1 = a0, a2 = a0, a3 = a0;
        #pragma unroll 16
        for (int f = 0; f < 64; f++) {
            float w = sW1[f * 64 + j];
            a0 += w * r0[f];
            a1 += w * r1[f];
            a2 += w * r2[f];
            a3 += w * r3[f];
        }
        sMid[(grp * 4 + 0) * 64 + j] = fmaxf(a0, 0.f);
        sMid[(grp * 4 + 1) * 64 + j] = fmaxf(a1, 0.f);
        sMid[(grp * 4 + 2) * 64 + j] = fmaxf(a2, 0.f);
        sMid[(grp * 4 + 3) * 64 + j] = fmaxf(a3, 0.f);
    }
    __syncthreads();
    // ---- stage B: g_H2 = sMid @ W2 + b2 ; accumulate batch stats ----
    const float* m0 = sMid + (grp * 4 + 0) * 64;
    const float* m1 = sMid + (grp * 4 + 1) * 64;
    const float* m2 = sMid + (grp * 4 + 2) * 64;
    const float* m3 = sMid + (grp * 4 + 3) * 64;
    float a0 = sB2[j], a1 = a0, a2 = a0, a3 = a0;
    #pragma unroll 16
    for (int f = 0; f < 64; f++) {
        float w = sW2[f * 64 + j];
        a0 += w * m0[f];
        a1 += w * m1[f];
        a2 += w * m2[f];
        a3 += w * m3[f];
    }
    int node0 = blockIdx.x * 16 + grp * 4;
    g_H2[(node0 + 0) * 64 + j] = a0;
    g_H2[(node0 + 1) * 64 + j] = a1;
    g_H2[(node0 + 2) * 64 + j] = a2;
    g_H2[(node0 + 3) * 64 + j] = a3;

    __shared__ float sS[256];
    __shared__ float sQ[256];
    sS[tid] = a0 + a1 + a2 + a3;
    sQ[tid] = a0 * a0 + a1 * a1 + a2 * a2 + a3 * a3;
    __syncthreads();
    if (grp == 0) {
        float S = sS[j] + sS[j + 64] + sS[j + 128] + sS[j + 192];
        float Q = sQ[j] + sQ[j + 64] + sQ[j + 128] + sQ[j + 192];
        atomicAdd(&g_stats[j], S);
        atomicAdd(&g_stats[64 + j], Q);
    }
}

// fold batch stats into per-channel scale/shift:  y = h*sc + sh
__global__ void bncoef_kernel(const float* __restrict__ gamma,
                              const float* __restrict__ beta) {
    int j = threadIdx.x;
    if (j < 64) {
        const float inv = 1.0f / (float)NN;
        float mean = g_stats[j] * inv;
        float var  = g_stats[64 + j] * inv - mean * mean;
        float sc = __ldg(gamma + j) * rsqrtf(var + 1e-5f);
        g_bn[j] = sc;
        g_bn[64 + j] = __ldg(beta + j) - mean * sc;
    }
}

// ===========================================================================
// apply BN+relu (+residual), float4-vectorized (4 consecutive channels/thread);
// MODE 0/1 also re-zero stats for the next layer.
//   MODE 0: g_H  = relu(bn(H2))                         (after L1)
//   MODE 1: g_H += relu(bn(H2))                         (after L2, residual)
//   MODE 2: out  = g_H + relu(bn(H2))                   (after L3 -> output)
// ===========================================================================
template<int MODE>
__global__ void apply_kernel(float* __restrict__ out) {
    if (MODE != 2 && blockIdx.x == 0 && threadIdx.x < 128)
        g_stats[threadIdx.x] = 0.0f;
    int i = blockIdx.x * blockDim.x + threadIdx.x;    // float4 index
    if (i >= NN * 16) return;
    int c = (i * 4) & 63;                             // first channel of the 4
    float4 h2 = ((const float4*)g_H2)[i];
    float4 v;
    v.x = fmaxf(h2.x * g_bn[c + 0] + g_bn[64 + c + 0], 0.0f);
    v.y = fmaxf(h2.y * g_bn[c + 1] + g_bn[64 + c + 1], 0.0f);
    v.z = fmaxf(h2.z * g_bn[c + 2] + g_bn[64 + c + 2], 0.0f);
    v.w = fmaxf(h2.w * g_bn[c + 3] + g_bn[64 + c + 3], 0.0f);
    if (MODE == 0) {
        ((float4*)g_H)[i] = v;
    } else if (MODE == 1) {
        float4 h = ((const float4*)g_H)[i];
        h.x += v.x; h.y += v.y; h.z += v.z; h.w += v.w;
        ((float4*)g_H)[i] = h;
    } else {
        float4 h = ((const float4*)g_H)[i];
        h.x += v.x; h.y += v.y; h.z += v.z; h.w += v.w;
        ((float4*)out)[i] = h;
    }
}

// ===========================================================================
extern "C" void kernel_launch(void* const* d_in, const int* in_sizes, int n_in,
                              void* d_out, int out_size) {
    const float* x    = (const float*)d_in[0];
    const int*   ei   = (const int*)d_in[1];      // int32 OR int64 (detected)
    const float* ew   = (const float*)d_in[2];
    const float* eps1 = (const float*)d_in[3];
    const float* W1a  = (const float*)d_in[4];
    const float* b1a  = (const float*)d_in[5];
    const float* W1b  = (const float*)d_in[6];
    const float* b1b  = (const float*)d_in[7];
    const float* g1   = (const float*)d_in[8];
    const float* be1  = (const float*)d_in[9];
    const float* epss = (const float*)d_in[10];
    const float* Wsa  = (const float*)d_in[11];
    const float* bsa  = (const float*)d_in[12];
    const float* Wsb  = (const float*)d_in[13];
    const float* bsb  = (const float*)d_in[14];
    const float* gs   = (const float*)d_in[15];
    const float* bes  = (const float*)d_in[16];
    float* out = (float*)d_out;

    const int E = in_sizes[1] / 2;

    const int TB = 256;
    const int grid_n    = (NN + TB - 1) / TB;
    const int grid_e    = (E + TB - 1) / TB;
    const int nb_scan   = (NN + 1023) / 1024;            // 98
    const int grid_p128 = (NN + 7) / 8;                  // 8 nodes/block
    const int grid_p64  = (NN + 15) / 16;                // 16 nodes/block
    const int grid_mlp  = NN / 16;
    const int grid_ap   = (NN * 16 + TB - 1) / TB;       // float4 elements

    // ---- Build CSC once (reused by all 3 layers) ----
    build_init_kernel<<<grid_n, TB>>>(ei);
    hist_kernel<<<grid_e, TB>>>(ei, E);
    scan1_kernel<<<nb_scan, 1024>>>(NN);
    scan2_kernel<<<1, 128>>>(nb_scan);
    scanadd_kernel<<<grid_n, TB>>>(E);
    scatter_kernel<<<grid_e, TB>>>(ei, ew, E);

    // ---- Layer 1 (F=128 -> H=64) ----
    pull128_kernel<<<grid_p128, TB>>>(x, eps1);
    mlp_kernel<128, true><<<grid_mlp, TB>>>(W1a, b1a);
    mlp_kernel<64, false><<<grid_mlp, TB>>>(W1b, b1b);
    bncoef_kernel<<<1, 64>>>(g1, be1);
    apply_kernel<0><<<grid_ap, TB>>>(out);

    // ---- Layer 2 (64 -> 64), residual ----
    pull64_kernel<<<grid_p64, TB>>>(epss + 0);
    mlp2_kernel<<<grid_mlp, TB>>>(Wsa, bsa, Wsb, bsb);
    bncoef_kernel<<<1, 64>>>(gs, bes);
    apply_kernel<1><<<grid_ap, TB>>>(out);

    // ---- Layer 3 (64 -> 64), residual -> output ----
    pull64_kernel<<<grid_p64, TB>>>(epss + 1);
    mlp2_kernel<<<grid_mlp, TB>>>(Wsa + 64 * 64, bsa + 64, Wsb + 64 * 64, bsb + 64);
    bncoef_kernel<<<1, 64>>>(gs + 64, bes + 64);
    apply_kernel<2><<<grid_ap, TB>>>(out);
}

// round 12
// speedup vs baseline: 1.0549x; 1.0549x over previous
#include <cuda_runtime.h>

#define NN 100000
#define EMAX 1600000
#define FF 128
#define HH 64

// ---- persistent scratch (no allocations allowed) ----
__device__ float g_AGG[NN * HH];       // aggregation output (all layers 64-wide now)
__device__ float g_H2 [NN * HH];       // after second linear (pre-BN)
__device__ float g_H  [NN * HH];       // node features (y=x@W1a, then post BN/relu/residual)
__device__ float g_stats[2 * HH];      // sum, sumsq per channel
__device__ float g_bn   [2 * HH];      // scale, shift per channel
__device__ int   g_is64;               // edge_index dtype flag (runtime-detected)
// CSC structure (built once per call, reused by all 3 layers)
__device__ int  g_rowptr[NN + 1];      // exclusive prefix of in-degrees
__device__ int  g_cursor[NN];          // counts during hist, then scatter cursors
__device__ int  g_blocksum[128];       // scan partials
__device__ int2 g_edges[EMAX];         // per-dst-grouped {src, bitcast(weight)}

// ===========================================================================
// build init: zero cursors; block 0 also detects edge_index dtype.
// int64 indices < 2^31 => all odd 32-bit words are zero.
// ===========================================================================
__global__ void build_init_kernel(const int* __restrict__ w) {
    if (blockIdx.x == 0 && threadIdx.x == 0) {
        int any = 0;
        #pragma unroll
        for (int i = 1; i < 128; i += 2) any |= w[i];
        g_is64 = (any == 0) ? 1 : 0;
    }
    int i = blockIdx.x * blockDim.x + threadIdx.x;
    if (i < NN) g_cursor[i] = 0;
}

__device__ __forceinline__ int load_src(const int* w, int E, int e, int is64) {
    return is64 ? __ldg(w + 2 * e) : __ldg(w + e);
}
__device__ __forceinline__ int load_dst(const int* w, int E, int e, int is64) {
    return is64 ? __ldg(w + 2 * (E + e)) : __ldg(w + E + e);
}

// ===========================================================================
// CSC build: hist -> scan1 -> scan2 -> scanAdd -> scatter
// ===========================================================================
__global__ void hist_kernel(const int* __restrict__ ei, int E) {
    int e = blockIdx.x * blockDim.x + threadIdx.x;
    if (e >= E) return;
    int is64 = g_is64;
    atomicAdd(&g_cursor[load_dst(ei, E, e, is64)], 1);
}

__global__ void scan1_kernel(int n) {
    __shared__ int tmp[1024];
    int i = blockIdx.x * 1024 + threadIdx.x;
    int v = (i < n) ? g_cursor[i] : 0;
    tmp[threadIdx.x] = v;
    __syncthreads();
    for (int off = 1; off < 1024; off <<= 1) {
        int t = (threadIdx.x >= off) ? tmp[threadIdx.x - off] : 0;
        __syncthreads();
        tmp[threadIdx.x] += t;
        __syncthreads();
    }
    if (i < n) g_rowptr[i] = tmp[threadIdx.x] - v;   // exclusive, block-local
    if (threadIdx.x == 1023) g_blocksum[blockIdx.x] = tmp[1023];
}

__global__ void scan2_kernel(int nb) {
    __shared__ int tmp[128];
    int v = (threadIdx.x < nb) ? g_blocksum[threadIdx.x] : 0;
    tmp[threadIdx.x] = v;
    __syncthreads();
    for (int off = 1; off < 128; off <<= 1) {
        int t = (threadIdx.x >= off) ? tmp[threadIdx.x - off] : 0;
        __syncthreads();
        tmp[threadIdx.x] += t;
        __syncthreads();
    }
    if (threadIdx.x < nb) g_blocksum[threadIdx.x] = tmp[threadIdx.x] - v;
}

__global__ void scanadd_kernel(int E) {
    int i = blockIdx.x * blockDim.x + threadIdx.x;
    if (i < NN) {
        int r = g_rowptr[i] + g_blocksum[i >> 10];
        g_rowptr[i] = r;
        g_cursor[i] = r;                  // scatter cursor
    }
    if (i == 0) g_rowptr[NN] = E;
}

__global__ void scatter_kernel(const int* __restrict__ ei,
                               const float* __restrict__ ew, int E) {
    int e = blockIdx.x * blockDim.x + threadIdx.x;
    if (e >= E) return;
    int is64 = g_is64;
    int s = load_src(ei, E, e, is64);
    int d = load_dst(ei, E, e, is64);
    float w = __ldg(ew + e);
    int pos = atomicAdd(&g_cursor[d], 1);
    g_edges[pos] = make_int2(s, __float_as_int(w));
}

// ===========================================================================
// pregemm: g_H = x @ W1a  (no bias/relu; linearity lets us aggregate 64-wide).
// Block 0 also zeroes batch-stat accumulators for layer 1.
// ===========================================================================
__global__ void pregemm_kernel(const float* __restrict__ x,
                               const float* __restrict__ W) {
    __shared__ float sW[128 * 64];
    __shared__ float sRow[16 * 128];
    if (blockIdx.x == 0 && threadIdx.x < 128) g_stats[threadIdx.x] = 0.0f;
    int tid = threadIdx.x;
    for (int i = tid; i < 128 * 16; i += 256)          // 128*64/4 float4s
        ((float4*)sW)[i] = __ldg(((const float4*)W) + i);
    long long base = (long long)blockIdx.x * (16 * 128 / 4);
    for (int i = tid; i < 16 * 128 / 4; i += 256)
        ((float4*)sRow)[i] = __ldg(((const float4*)x) + base + i);
    __syncthreads();

    int j = tid & 63, grp = tid >> 6;
    const float* r0 = sRow + (grp * 4 + 0) * 128;
    const float* r1 = sRow + (grp * 4 + 1) * 128;
    const float* r2 = sRow + (grp * 4 + 2) * 128;
    const float* r3 = sRow + (grp * 4 + 3) * 128;
    float a0 = 0.f, a1 = 0.f, a2 = 0.f, a3 = 0.f;
    #pragma unroll 16
    for (int f = 0; f < 128; f++) {
        float w = sW[f * 64 + j];
        a0 += w * r0[f];
        a1 += w * r1[f];
        a2 += w * r2[f];
        a3 += w * r3[f];
    }
    int node0 = blockIdx.x * 16 + grp * 4;
    g_H[(node0 + 0) * 64 + j] = a0;
    g_H[(node0 + 1) * 64 + j] = a1;
    g_H[(node0 + 2) * 64 + j] = a2;
    g_H[(node0 + 3) * 64 + j] = a3;
}

// ===========================================================================
// Pull aggregation, F=64 (reads g_H): 16 lanes per node, 2 nodes per warp.
//   g_AGG[node] = (1+eps)*h[node] + sum_edges w * h[src]
// Edge loop unrolled x4: 4 independent gathers in flight.
// ===========================================================================
__global__ void pull64_kernel(const float* __restrict__ eps) {
    int node = blockIdx.x * (blockDim.x >> 4) + (threadIdx.x >> 4);
    if (node >= NN) return;
    int l = threadIdx.x & 15;
    int beg = __ldg(g_rowptr + node);
    int end = __ldg(g_rowptr + node + 1);
    float s = 1.0f + __ldg(eps);
    float4 acc = ((const float4*)g_H)[(size_t)node * 16 + l];
    acc.x *= s; acc.y *= s; acc.z *= s; acc.w *= s;
    int p = beg;
    for (; p + 4 <= end; p += 4) {
        int2 e0 = __ldg(g_edges + p);
        int2 e1 = __ldg(g_edges + p + 1);
        int2 e2 = __ldg(g_edges + p + 2);
        int2 e3 = __ldg(g_edges + p + 3);
        float4 v0 = ((const float4*)g_H)[(size_t)e0.x * 16 + l];
        float4 v1 = ((const float4*)g_H)[(size_t)e1.x * 16 + l];
        float4 v2 = ((const float4*)g_H)[(size_t)e2.x * 16 + l];
        float4 v3 = ((const float4*)g_H)[(size_t)e3.x * 16 + l];
        float w0 = __int_as_float(e0.y), w1 = __int_as_float(e1.y);
        float w2 = __int_as_float(e2.y), w3 = __int_as_float(e3.y);
        acc.x += w0 * v0.x; acc.y += w0 * v0.y; acc.z += w0 * v0.z; acc.w += w0 * v0.w;
        acc.x += w1 * v1.x; acc.y += w1 * v1.y; acc.z += w1 * v1.z; acc.w += w1 * v1.w;
        acc.x += w2 * v2.x; acc.y += w2 * v2.y; acc.z += w2 * v2.z; acc.w += w2 * v2.w;
        acc.x += w3 * v3.x; acc.y += w3 * v3.y; acc.z += w3 * v3.z; acc.w += w3 * v3.w;
    }
    for (; p < end; p++) {
        int2 e0 = __ldg(g_edges + p);
        float w0 = __int_as_float(e0.y);
        float4 v0 = ((const float4*)g_H)[(size_t)e0.x * 16 + l];
        acc.x += w0 * v0.x; acc.y += w0 * v0.y;
        acc.z += w0 * v0.z; acc.w += w0 * v0.w;
    }
    ((float4*)g_AGG)[(size_t)node * 16 + l] = acc;
}

// ===========================================================================
// Layer-1 fused MLP (after linearity transform):
//   g_H2 = relu(g_AGG + b1a) @ W1b + b1b   + batch-stat accum
// relu(+bias) fused into the load loop (no separate sRow staging).
// ===========================================================================
__global__ void mlp1_kernel(const float* __restrict__ b1,
                            const float* __restrict__ W2,
                            const float* __restrict__ b2) {
    __shared__ float sW2[64 * 64];
    __shared__ float sMid[16 * 64];
    __shared__ float sB2[64];
    int tid = threadIdx.x;
    for (int i = tid; i < 64 * 16; i += 256)           // 64*64/4 float4s
        ((float4*)sW2)[i] = __ldg(((const float4*)W2) + i);
    if (tid < 64) sB2[tid] = __ldg(b2 + tid);
    long long base = (long long)blockIdx.x * (16 * 64 / 4);
    for (int i = tid; i < 16 * 64 / 4; i += 256) {
        float4 v = __ldg(((const float4*)g_AGG) + base + i);
        int c = (i * 4) & 63;
        v.x = fmaxf(v.x + __ldg(b1 + c + 0), 0.0f);
        v.y = fmaxf(v.y + __ldg(b1 + c + 1), 0.0f);
        v.z = fmaxf(v.z + __ldg(b1 + c + 2), 0.0f);
        v.w = fmaxf(v.w + __ldg(b1 + c + 3), 0.0f);
        ((float4*)sMid)[i] = v;
    }
    __syncthreads();

    int j = tid & 63, grp = tid >> 6;
    const float* m0 = sMid + (grp * 4 + 0) * 64;
    const float* m1 = sMid + (grp * 4 + 1) * 64;
    const float* m2 = sMid + (grp * 4 + 2) * 64;
    const float* m3 = sMid + (grp * 4 + 3) * 64;
    float a0 = sB2[j], a1 = a0, a2 = a0, a3 = a0;
    #pragma unroll 16
    for (int f = 0; f < 64; f++) {
        float w = sW2[f * 64 + j];
        a0 += w * m0[f];
        a1 += w * m1[f];
        a2 += w * m2[f];
        a3 += w * m3[f];
    }
    int node0 = blockIdx.x * 16 + grp * 4;
    g_H2[(node0 + 0) * 64 + j] = a0;
    g_H2[(node0 + 1) * 64 + j] = a1;
    g_H2[(node0 + 2) * 64 + j] = a2;
    g_H2[(node0 + 3) * 64 + j] = a3;

    __shared__ float sS[256];
    __shared__ float sQ[256];
    sS[tid] = a0 + a1 + a2 + a3;
    sQ[tid] = a0 * a0 + a1 * a1 + a2 * a2 + a3 * a3;
    __syncthreads();
    if (grp == 0) {
        float S = sS[j] + sS[j + 64] + sS[j + 128] + sS[j + 192];
        float Q = sQ[j] + sQ[j + 64] + sQ[j + 128] + sQ[j + 192];
        atomicAdd(&g_stats[j], S);
        atomicAdd(&g_stats[64 + j], Q);
    }
}

// ===========================================================================
// Fused 64->64->64 MLP (layers 2,3): both GEMMs in one kernel.
//   g_H2 = (relu(g_AGG @ W1 + b1)) @ W2 + b2   + batch-stat accum
// ===========================================================================
__global__ void mlp2_kernel(const float* __restrict__ W1,
                            const float* __restrict__ b1,
                            const float* __restrict__ W2,
                            const float* __restrict__ b2) {
    __shared__ float sW1[64 * 64];
    __shared__ float sW2[64 * 64];
    __shared__ float sRow[16 * 64];
    __shared__ float sMid[16 * 64];
    __shared__ float sB1[64];
    __shared__ float sB2[64];
    int tid = threadIdx.x;
    for (int i = tid; i < 64 * 16; i += 256) {         // 64*64/4 float4s
        ((float4*)sW1)[i] = __ldg(((const float4*)W1) + i);
        ((float4*)sW2)[i] = __ldg(((const float4*)W2) + i);
    }
    if (tid < 64) { sB1[tid] = __ldg(b1 + tid); sB2[tid] = __ldg(b2 + tid); }
    long long base = (long long)blockIdx.x * (16 * 64 / 4);
    for (int i = tid; i < 16 * 64 / 4; i += 256)
        ((float4*)sRow)[i] = __ldg(((const float4*)g_AGG) + base + i);
    __syncthreads();

    int j = tid & 63, grp = tid >> 6;
    // ---- stage A: sMid = relu(sRow @ W1 + b1) ----
    {
        const float* r0 = sRow + (grp * 4 + 0) * 64;
        const float* r1 = sRow + (grp * 4 + 1) * 64;
        const float* r2 = sRow + (grp * 4 + 2) * 64;
        const float* r3 = sRow + (grp * 4 + 3) * 64;
        float a0 = sB1[j], a1 = a0, a2 = a0, a3 = a0;
        #pragma unroll 16
        for (int f = 0; f < 64; f++) {
            float w = sW1[f * 64 + j];
            a0 += w * r0[f];
            a1 += w * r1[f];
            a2 += w * r2[f];
            a3 += w * r3[f];
        }
        sMid[(grp * 4 + 0) * 64 + j] = fmaxf(a0, 0.f);
        sMid[(grp * 4 + 1) * 64 + j] = fmaxf(a1, 0.f);
        sMid[(grp * 4 + 2) * 64 + j] = fmaxf(a2, 0.f);
        sMid[(grp * 4 + 3) * 64 + j] = fmaxf(a3, 0.f);
    }
    __syncthreads();
    // ---- stage B: g_H2 = sMid @ W2 + b2 ; accumulate batch stats ----
    const float* m0 = sMid + (grp * 4 + 0) * 64;
    const float* m1 = sMid + (grp * 4 + 1) * 64;
    const float* m2 = sMid + (grp * 4 + 2) * 64;
    const float* m3 = sMid + (grp * 4 + 3) * 64;
    float a0 = sB2[j], a1 = a0, a2 = a0, a3 = a0;
    #pragma unroll 16
    for (int f = 0; f < 64; f++) {
        float w = sW2[f * 64 + j];
        a0 += w * m0[f];
        a1 += w * m1[f];
        a2 += w * m2[f];
        a3 += w * m3[f];
    }
    int node0 = blockIdx.x * 16 + grp * 4;
    g_H2[(node0 + 0) * 64 + j] = a0;
    g_H2[(node0 + 1) * 64 + j] = a1;
    g_H2[(node0 + 2) * 64 + j] = a2;
    g_H2[(node0 + 3) * 64 + j] = a3;

    __shared__ float sS[256];
    __shared__ float sQ[256];
    sS[tid] = a0 + a1 + a2 + a3;
    sQ[tid] = a0 * a0 + a1 * a1 + a2 * a2 + a3 * a3;
    __syncthreads();
    if (grp == 0) {
        float S = sS[j] + sS[j + 64] + sS[j + 128] + sS[j + 192];
        float Q = sQ[j] + sQ[j + 64] + sQ[j + 128] + sQ[j + 192];
        atomicAdd(&g_stats[j], S);
        atomicAdd(&g_stats[64 + j], Q);
    }
}

// fold batch stats into per-channel scale/shift:  y = h*sc + sh
__global__ void bncoef_kernel(const float* __restrict__ gamma,
                              const float* __restrict__ beta) {
    int j = threadIdx.x;
    if (j < 64) {
        const float inv = 1.0f / (float)NN;
        float mean = g_stats[j] * inv;
        float var  = g_stats[64 + j] * inv - mean * mean;
        float sc = __ldg(gamma + j) * rsqrtf(var + 1e-5f);
        g_bn[j] = sc;
        g_bn[64 + j] = __ldg(beta + j) - mean * sc;
    }
}

// ===========================================================================
// apply BN+relu (+residual), float4-vectorized; MODE 0/1 re-zero stats.
//   MODE 0: g_H  = relu(bn(H2))                         (after L1)
//   MODE 1: g_H += relu(bn(H2))                         (after L2, residual)
//   MODE 2: out  = g_H + relu(bn(H2))                   (after L3 -> output)
// ===========================================================================
template<int MODE>
__global__ void apply_kernel(float* __restrict__ out) {
    if (MODE != 2 && blockIdx.x == 0 && threadIdx.x < 128)
        g_stats[threadIdx.x] = 0.0f;
    int i = blockIdx.x * blockDim.x + threadIdx.x;    // float4 index
    if (i >= NN * 16) return;
    int c = (i * 4) & 63;                             // first channel of the 4
    float4 h2 = ((const float4*)g_H2)[i];
    float4 v;
    v.x = fmaxf(h2.x * g_bn[c + 0] + g_bn[64 + c + 0], 0.0f);
    v.y = fmaxf(h2.y * g_bn[c + 1] + g_bn[64 + c + 1], 0.0f);
    v.z = fmaxf(h2.z * g_bn[c + 2] + g_bn[64 + c + 2], 0.0f);
    v.w = fmaxf(h2.w * g_bn[c + 3] + g_bn[64 + c + 3], 0.0f);
    if (MODE == 0) {
        ((float4*)g_H)[i] = v;
    } else if (MODE == 1) {
        float4 h = ((const float4*)g_H)[i];
        h.x += v.x; h.y += v.y; h.z += v.z; h.w += v.w;
        ((float4*)g_H)[i] = h;
    } else {
        float4 h = ((const float4*)g_H)[i];
        h.x += v.x; h.y += v.y; h.z += v.z; h.w += v.w;
        ((float4*)out)[i] = h;
    }
}

// ===========================================================================
extern "C" void kernel_launch(void* const* d_in, const int* in_sizes, int n_in,
                              void* d_out, int out_size) {
    const float* x    = (const float*)d_in[0];
    const int*   ei   = (const int*)d_in[1];      // int32 OR int64 (detected)
    const float* ew   = (const float*)d_in[2];
    const float* eps1 = (const float*)d_in[3];
    const float* W1a  = (const float*)d_in[4];
    const float* b1a  = (const float*)d_in[5];
    const float* W1b  = (const float*)d_in[6];
    const float* b1b  = (const float*)d_in[7];
    const float* g1   = (const float*)d_in[8];
    const float* be1  = (const float*)d_in[9];
    const float* epss = (const float*)d_in[10];
    const float* Wsa  = (const float*)d_in[11];
    const float* bsa  = (const float*)d_in[12];
    const float* Wsb  = (const float*)d_in[13];
    const float* bsb  = (const float*)d_in[14];
    const float* gs   = (const float*)d_in[15];
    const float* bes  = (const float*)d_in[16];
    float* out = (float*)d_out;

    const int E = in_sizes[1] / 2;

    const int TB = 256;
    const int grid_n    = (NN + TB - 1) / TB;
    const int grid_e    = (E + TB - 1) / TB;
    const int nb_scan   = (NN + 1023) / 1024;            // 98
    const int grid_p64  = (NN + 15) / 16;                // 16 nodes/block
    const int grid_mlp  = NN / 16;
    const int grid_ap   = (NN * 16 + TB - 1) / TB;       // float4 elements

    // ---- Build CSC once (reused by all 3 layers) ----
    build_init_kernel<<<grid_n, TB>>>(ei);
    hist_kernel<<<grid_e, TB>>>(ei, E);
    scan1_kernel<<<nb_scan, 1024>>>(NN);
    scan2_kernel<<<1, 128>>>(nb_scan);
    scanadd_kernel<<<grid_n, TB>>>(E);
    scatter_kernel<<<grid_e, TB>>>(ei, ew, E);

    // ---- Layer 1 (F=128 -> H=64), aggregation moved past W1a via linearity ----
    pregemm_kernel<<<grid_mlp, TB>>>(x, W1a);         // g_H = x @ W1a ; zero stats
    pull64_kernel<<<grid_p64, TB>>>(eps1);            // g_AGG = (1+eps1)y + Σ w y
    mlp1_kernel<<<grid_mlp, TB>>>(b1a, W1b, b1b);     // relu(agg+b1a)@W1b+b1b
    bncoef_kernel<<<1, 64>>>(g1, be1);
    apply_kernel<0><<<grid_ap, TB>>>(out);

    // ---- Layer 2 (64 -> 64), residual ----
    pull64_kernel<<<grid_p64, TB>>>(epss + 0);
    mlp2_kernel<<<grid_mlp, TB>>>(Wsa, bsa, Wsb, bsb);
    bncoef_kernel<<<1, 64>>>(gs, bes);
    apply_kernel<1><<<grid_ap, TB>>>(out);

    // ---- Layer 3 (64 -> 64), residual -> output ----
    pull64_kernel<<<grid_p64, TB>>>(epss + 1);
    mlp2_kernel<<<grid_mlp, TB>>>(Wsa + 64 * 64, bsa + 64, Wsb + 64 * 64, bsb + 64);
    bncoef_kernel<<<1, 64>>>(gs + 64, bes + 64);
    apply_kernel<2><<<grid_ap, TB>>>(out);
}